// round 11
// baseline (speedup 1.0000x reference)
#include <cuda_runtime.h>
#include <cuda_fp16.h>
#include <cstdint>

#define HW 16384
#define NTH 1024      // 32 warps: MW=8 (M) x PW=4 (pixels)
#define BPITCH 136    // B smem pitch (halfs)
#define YPITCH 132    // Y smem pitch (floats)
#define WPITCH 40     // W smem pitch (halfs) per 32-k chunk
#define NCHUNK 16     // W1[0..7] then W2[8..15]
#define CHUNK_B 20480
#define CHUNK_E 10240

// ---- smem layout (bytes) ----
#define SM_BH   0                 // 69632 (X/H fp16; aliased by Ys fp32 after GEMM2)
#define SM_W    69632             // 4 x 20480 ring -> ends 151552
#define SM_MSK  151552
#define SM_POS  151680            // 128 x int16
#define SM_FLG  151936
#define SM_TOTAL 152064

__device__ __align__(16) __half g_Ws[NCHUNK * CHUNK_E];

// ---------------- weight prep ----------------
extern "C" __global__ void prep_weights_kernel(const float* __restrict__ W1,
                                               const float* __restrict__ W2)
{
    int k = blockIdx.x;
    int m = threadIdx.x;
    int ch = k >> 5, kk = k & 31;
    g_Ws[ch * CHUNK_E + m * WPITCH + kk]       = __float2half_rn(W1[k * 256 + m]);
    g_Ws[(8 + ch) * CHUNK_E + m * WPITCH + kk] = __float2half_rn(W2[k * 256 + m]);
}

// ---------------- helpers ----------------
__device__ __forceinline__ void ldsm_x4(uint32_t* r, uint32_t addr) {
    asm volatile("ldmatrix.sync.aligned.m8n8.x4.shared.b16 {%0,%1,%2,%3}, [%4];"
                 : "=r"(r[0]), "=r"(r[1]), "=r"(r[2]), "=r"(r[3]) : "r"(addr));
}
__device__ __forceinline__ void ldsm_x4_t(uint32_t* r, uint32_t addr) {
    asm volatile("ldmatrix.sync.aligned.m8n8.x4.trans.shared.b16 {%0,%1,%2,%3}, [%4];"
                 : "=r"(r[0]), "=r"(r[1]), "=r"(r[2]), "=r"(r[3]) : "r"(addr));
}
__device__ __forceinline__ void mma_f16(float* d, const uint32_t* a, const uint32_t* b) {
    asm volatile("mma.sync.aligned.m16n8k16.row.col.f32.f16.f16.f32 "
                 "{%0,%1,%2,%3}, {%4,%5,%6,%7}, {%8,%9}, {%0,%1,%2,%3};"
                 : "+f"(d[0]), "+f"(d[1]), "+f"(d[2]), "+f"(d[3])
                 : "r"(a[0]), "r"(a[1]), "r"(a[2]), "r"(a[3]), "r"(b[0]), "r"(b[1]));
}
__device__ __forceinline__ void cp16(uint32_t dst, const void* src) {
    asm volatile("cp.async.cg.shared.global [%0], [%1], 16;" :: "r"(dst), "l"(src));
}
__device__ __forceinline__ uint32_t hpack(__half a, __half b) {
    __half2 t = __halves2half2(a, b);
    return *reinterpret_cast<uint32_t*>(&t);
}
__device__ __forceinline__ void copy_chunk(uint32_t sb, int ch, int tid) {
    uint32_t dst = sb + SM_W + (ch & 3) * CHUNK_B;
    const char* src = (const char*)(g_Ws + (size_t)ch * CHUNK_E);
    #pragma unroll
    for (int t = 0; t < 2; t++) {
        int line = tid + t * NTH;
        if (line < 1280) cp16(dst + line * 16, src + line * 16);
    }
}

// ---------------- main fused masked-MLP kernel ----------------
extern "C" __global__ void __launch_bounds__(NTH, 1)
mlp_mma_kernel(const float* __restrict__ x,
               const void* __restrict__ mask,
               const float* __restrict__ b1g,
               const float* __restrict__ b2g,
               float* __restrict__ out)
{
    extern __shared__ char smc[];
    const uint32_t sb = (uint32_t)__cvta_generic_to_shared(smc);
    int* flg = (int*)(smc + SM_FLG);
    short* pos = (short*)(smc + SM_POS);

    const int tid = threadIdx.x, lane = tid & 31, wid = tid >> 5;
    const int wd = wid >> 2, wp = wid & 3;       // wd 0..7 (32 M rows), wp 0..3 (tiles 4s+wp)
    const int g = lane >> 2, tc = lane & 3;
    const int l15 = lane & 15, l16 = (lane >> 4) * 8;
    const int b = blockIdx.x >> 7, p0 = (blockIdx.x & 127) * 128;
    const float* xb = x + (size_t)b * 256 * HW + p0;
    const int gi0 = b * HW + p0;

    // ---- kick off weight pipeline immediately ----
    copy_chunk(sb, 0, tid);
    asm volatile("cp.async.commit_group;" ::: "memory");
    copy_chunk(sb, 1, tid);
    asm volatile("cp.async.commit_group;" ::: "memory");

    // ---- per-CTA mask dtype detection ----
    if (tid < 32) {
        unsigned w = ((const unsigned*)mask)[gi0 / 4 + tid];
        bool fl = (w == 0x3F800000u);
        bool by = (w > 1u) && !fl;
        unsigned bb = __ballot_sync(0xFFFFFFFFu, by);
        if (tid == 0) flg[0] = bb ? 1 : 0;
    }
    __syncthreads();

    if (tid < 128) {
        int mv;
        if (flg[0]) mv = (((const unsigned char*)mask)[gi0 + tid] != 0);
        else        mv = (((const int*)mask)[gi0 + tid] != 0);
        smc[SM_MSK + tid] = (char)mv;
    }
    __syncthreads();

    // ---- warp 0: prefix scan -> per-pixel pos[] / nc ----
    if (wid == 0) {
        int base = lane * 4;
        int m0 = smc[SM_MSK + base], m1 = smc[SM_MSK + base + 1];
        int m2 = smc[SM_MSK + base + 2], m3 = smc[SM_MSK + base + 3];
        int c = m0 + m1 + m2 + m3;
        int sc = c;
        #pragma unroll
        for (int o = 1; o < 32; o <<= 1) {
            int t = __shfl_up_sync(0xFFFFFFFFu, sc, o);
            if (lane >= o) sc += t;
        }
        int run = sc - c;
        pos[base]     = (short)run; run += m0;
        pos[base + 1] = (short)run; run += m1;
        pos[base + 2] = (short)run; run += m2;
        pos[base + 3] = (short)run; run += m3;
        if (lane == 31) flg[1] = run;
    }
    __syncthreads();
    const int nc = flg[1];
    const int ntiles = (nc + 15) >> 4;

    // ---- X load + fp16 convert + compacted store ----
    __half* Bh = (__half*)(smc + SM_BH);
    #pragma unroll 4
    for (int it = 0; it < 8; it++) {
        int e = tid + it * NTH;
        int c = e >> 5;
        int q = (e & 31) * 4;
        float4 v = *(const float4*)(xb + (size_t)c * HW + q);
        float vv[4] = {v.x, v.y, v.z, v.w};
        #pragma unroll
        for (int i = 0; i < 4; i++) {
            if (smc[SM_MSK + q + i])
                Bh[c * BPITCH + pos[q + i]] = __float2half_rn(vv[i]);
        }
    }

    float acc[2][2][2][4];   // [m-frag][s-tile][jl][r]
    #pragma unroll
    for (int i = 0; i < 2; i++)
        #pragma unroll
        for (int s = 0; s < 2; s++)
            #pragma unroll
            for (int jl = 0; jl < 2; jl++)
                #pragma unroll
                for (int r = 0; r < 4; r++) acc[i][s][jl][r] = 0.f;

    // warp-constant smem address bases (hoisted out of the K loop)
    const uint32_t a_base = (uint32_t)((wd * 32 + l15) * WPITCH + l16) * 2;
    const uint32_t b_base = sb + SM_BH + (uint32_t)(l15 * BPITCH + wp * 16 + l16) * 2;

    // ---- unified 16-chunk K loop: chunks 0-7 = GEMM1, 8-15 = GEMM2 ----
    #pragma unroll 1
    for (int kc = 0; kc < NCHUNK; kc++) {
        if (kc + 2 < NCHUNK) copy_chunk(sb, kc + 2, tid);
        asm volatile("cp.async.commit_group;" ::: "memory");
        asm volatile("cp.async.wait_group 2;" ::: "memory");
        __syncthreads();

        if (kc == 8) {
            // ---- H epilogue: bias + relu -> fp16 into Bh ----
            #pragma unroll
            for (int i = 0; i < 2; i++) {
                int r0 = wd * 32 + i * 16 + g;
                float bv0 = b1g[r0], bv1 = b1g[r0 + 8];
                #pragma unroll
                for (int s = 0; s < 2; s++) {
                    int tt = 4 * s + wp;
                    if (tt >= ntiles) break;
                    #pragma unroll
                    for (int jl = 0; jl < 2; jl++) {
                        int px = tt * 16 + jl * 8 + tc * 2;
                        float h00 = fmaxf(acc[i][s][jl][0] + bv0, 0.f);
                        float h01 = fmaxf(acc[i][s][jl][1] + bv0, 0.f);
                        float h10 = fmaxf(acc[i][s][jl][2] + bv1, 0.f);
                        float h11 = fmaxf(acc[i][s][jl][3] + bv1, 0.f);
                        *(uint32_t*)&Bh[r0 * BPITCH + px] =
                            hpack(__float2half_rn(h00), __float2half_rn(h01));
                        *(uint32_t*)&Bh[(r0 + 8) * BPITCH + px] =
                            hpack(__float2half_rn(h10), __float2half_rn(h11));
                        #pragma unroll
                        for (int r = 0; r < 4; r++) acc[i][s][jl][r] = 0.f;
                    }
                }
            }
            __syncthreads();
        }

        // ---- compute chunk kc ----
        const uint32_t wb = sb + SM_W + (kc & 3) * CHUNK_B + a_base;
        const uint32_t bb = b_base + (uint32_t)((kc & 7) * 32) * (BPITCH * 2);
        #pragma unroll
        for (int ks = 0; ks < 2; ks++) {
            uint32_t a0[4], a1[4];
            ldsm_x4(a0, wb + ks * 32);
            ldsm_x4(a1, wb + ks * 32 + 16 * WPITCH * 2);
            const uint32_t bks = bb + (uint32_t)(ks * 16) * (BPITCH * 2);
            #pragma unroll
            for (int s = 0; s < 2; s++) {
                int tt = 4 * s + wp;
                if (tt >= ntiles) break;
                uint32_t bh[4];
                ldsm_x4_t(bh, bks + (uint32_t)(s * 64) * 2);
                mma_f16(acc[0][s][0], a0, &bh[0]);
                mma_f16(acc[1][s][0], a1, &bh[0]);
                mma_f16(acc[0][s][1], a0, &bh[2]);
                mma_f16(acc[1][s][1], a1, &bh[2]);
            }
        }
    }

    // ---- stage Y (bias added) into smem, aliasing Bh + W ring ----
    __syncthreads();
    float* Ys = (float*)(smc + SM_BH);   // [256][YPITCH] fp32
    #pragma unroll
    for (int i = 0; i < 2; i++) {
        int r0 = wd * 32 + i * 16 + g;
        float bv0 = b2g[r0], bv1 = b2g[r0 + 8];
        #pragma unroll
        for (int s = 0; s < 2; s++) {
            int tt = 4 * s + wp;
            if (tt >= ntiles) break;
            #pragma unroll
            for (int jl = 0; jl < 2; jl++) {
                int pc = tt * 16 + jl * 8 + tc * 2;
                if (pc < nc) {
                    Ys[r0 * YPITCH + pc]       = acc[i][s][jl][0] + bv0;
                    Ys[(r0 + 8) * YPITCH + pc] = acc[i][s][jl][2] + bv1;
                }
                if (pc + 1 < nc) {
                    Ys[r0 * YPITCH + pc + 1]       = acc[i][s][jl][1] + bv0;
                    Ys[(r0 + 8) * YPITCH + pc + 1] = acc[i][s][jl][3] + bv1;
                }
            }
        }
    }
    __syncthreads();

    // ---- blended coalesced output: out = mask ? Y : x ----
    float* ob = out + (size_t)b * 256 * HW + p0;
    #pragma unroll 4
    for (int it = 0; it < 16; it++) {
        int e2 = tid + it * NTH;
        int c = e2 >> 6;
        int q = (e2 & 63) * 2;
        float2 v = *(const float2*)(xb + (size_t)c * HW + q);
        float2 o = v;
        if (smc[SM_MSK + q])     o.x = Ys[c * YPITCH + pos[q]];
        if (smc[SM_MSK + q + 1]) o.y = Ys[c * YPITCH + pos[q + 1]];
        *(float2*)(ob + (size_t)c * HW + q) = o;
    }
}

extern "C" void kernel_launch(void* const* d_in, const int* in_sizes, int n_in,
                              void* d_out, int out_size)
{
    const float* x    = (const float*)d_in[0];
    const void*  mask = d_in[1];
    const float* W1   = (const float*)d_in[2];
    const float* b1   = (const float*)d_in[3];
    const float* W2   = (const float*)d_in[4];
    const float* b2   = (const float*)d_in[5];
    float*       out  = (float*)d_out;

    prep_weights_kernel<<<256, 256>>>(W1, W2);

    cudaFuncSetAttribute(mlp_mma_kernel,
                         cudaFuncAttributeMaxDynamicSharedMemorySize, SM_TOTAL);
    mlp_mma_kernel<<<2048, NTH, SM_TOTAL>>>(x, mask, b1, b2, out);
}

// round 13
// speedup vs baseline: 1.1362x; 1.1362x over previous
#include <cuda_runtime.h>
#include <cuda_fp16.h>
#include <cstdint>

#define HW 16384
#define NTH 1024      // 32 warps: MW=16 (M) x PW=2 (pixels)  [R10 grid — validated]
#define BPITCH 136    // B smem pitch (halfs)
#define YPITCH 132    // Y smem pitch (floats)
#define WPITCH 72     // W smem pitch (halfs) per 64-k chunk (36 words ≡ 4 mod 32: conflict-free ldsm)
#define NCHUNK 8      // 8 chunks of k=64: W1[0..3] then W2[4..7]
#define CHUNK_B 36864 // bytes per chunk
#define CHUNK_E 18432 // half elems per chunk

// ---- smem layout (bytes) ----
#define SM_BH   0                 // 69632 (X/H fp16; aliased by Ys fp32 after GEMM2)
#define SM_W    69632             // 2 x 36864 ping-pong -> ends 143360
#define SM_MSK  143360            // 128
#define SM_POS  143488            // 128 x int16
#define SM_FLG  143744            // ints
#define SM_TOTAL 143872

__device__ __align__(16) __half g_Ws[NCHUNK * CHUNK_E];

// ---------------- weight prep: transpose + fp16, k=64 chunked layout ----------------
extern "C" __global__ void prep_weights_kernel(const float* __restrict__ W1,
                                               const float* __restrict__ W2)
{
    int k = blockIdx.x;      // input channel (K dim of WT)
    int m = threadIdx.x;     // output channel
    int ch = k >> 6, kk = k & 63;
    g_Ws[ch * CHUNK_E + m * WPITCH + kk]       = __float2half_rn(W1[k * 256 + m]);
    g_Ws[(4 + ch) * CHUNK_E + m * WPITCH + kk] = __float2half_rn(W2[k * 256 + m]);
}

// ---------------- helpers ----------------
__device__ __forceinline__ void ldsm_x4(uint32_t* r, uint32_t addr) {
    asm volatile("ldmatrix.sync.aligned.m8n8.x4.shared.b16 {%0,%1,%2,%3}, [%4];"
                 : "=r"(r[0]), "=r"(r[1]), "=r"(r[2]), "=r"(r[3]) : "r"(addr));
}
__device__ __forceinline__ void ldsm_x4_t(uint32_t* r, uint32_t addr) {
    asm volatile("ldmatrix.sync.aligned.m8n8.x4.trans.shared.b16 {%0,%1,%2,%3}, [%4];"
                 : "=r"(r[0]), "=r"(r[1]), "=r"(r[2]), "=r"(r[3]) : "r"(addr));
}
__device__ __forceinline__ void mma_f16(float* d, const uint32_t* a, const uint32_t* b) {
    asm volatile("mma.sync.aligned.m16n8k16.row.col.f32.f16.f16.f32 "
                 "{%0,%1,%2,%3}, {%4,%5,%6,%7}, {%8,%9}, {%0,%1,%2,%3};"
                 : "+f"(d[0]), "+f"(d[1]), "+f"(d[2]), "+f"(d[3])
                 : "r"(a[0]), "r"(a[1]), "r"(a[2]), "r"(a[3]), "r"(b[0]), "r"(b[1]));
}
__device__ __forceinline__ void cp16(uint32_t dst, const void* src) {
    asm volatile("cp.async.cg.shared.global [%0], [%1], 16;" :: "r"(dst), "l"(src));
}
__device__ __forceinline__ uint32_t hpack(__half a, __half b) {
    __half2 t = __halves2half2(a, b);
    return *reinterpret_cast<uint32_t*>(&t);
}
__device__ __forceinline__ void copy_chunk(uint32_t sb, int ch, int tid) {
    uint32_t dst = sb + SM_W + (ch & 1) * CHUNK_B;
    const char* src = (const char*)(g_Ws + (size_t)ch * CHUNK_E);
    #pragma unroll
    for (int t = 0; t < 3; t++) {
        int line = tid + t * NTH;          // 2304 lines of 16B
        if (line < 2304) cp16(dst + line * 16, src + line * 16);
    }
}

// ---------------- main fused masked-MLP kernel ----------------
extern "C" __global__ void __launch_bounds__(NTH, 1)
mlp_mma_kernel(const float* __restrict__ x,
               const void* __restrict__ mask,
               const float* __restrict__ b1g,
               const float* __restrict__ b2g,
               float* __restrict__ out)
{
    extern __shared__ char smc[];
    const uint32_t sb = (uint32_t)__cvta_generic_to_shared(smc);
    int* flg = (int*)(smc + SM_FLG);
    short* pos = (short*)(smc + SM_POS);

    const int tid = threadIdx.x, lane = tid & 31, wid = tid >> 5;
    const int wd = wid >> 1, wp = wid & 1;       // wd 0..15 (16 M rows), wp 0..1 (tiles 2s+wp)
    const int g = lane >> 2, tc = lane & 3;
    const int l15 = lane & 15, l16 = (lane >> 4) * 8;
    const int b = blockIdx.x >> 7, p0 = (blockIdx.x & 127) * 128;
    const float* xb = x + (size_t)b * 256 * HW + p0;
    const int gi0 = b * HW + p0;

    // ---- kick off first weight chunk immediately ----
    copy_chunk(sb, 0, tid);
    asm volatile("cp.async.commit_group;" ::: "memory");

    // ---- per-CTA mask dtype detection ----
    if (tid < 32) {
        unsigned w = ((const unsigned*)mask)[gi0 / 4 + tid];
        bool fl = (w == 0x3F800000u);
        bool by = (w > 1u) && !fl;
        unsigned bb = __ballot_sync(0xFFFFFFFFu, by);
        if (tid == 0) flg[0] = bb ? 1 : 0;
    }
    __syncthreads();

    if (tid < 128) {
        int mv;
        if (flg[0]) mv = (((const unsigned char*)mask)[gi0 + tid] != 0);
        else        mv = (((const int*)mask)[gi0 + tid] != 0);
        smc[SM_MSK + tid] = (char)mv;
    }
    __syncthreads();

    // ---- warp 0: prefix scan -> per-pixel pos[] / nc ----
    if (wid == 0) {
        int base = lane * 4;
        int m0 = smc[SM_MSK + base], m1 = smc[SM_MSK + base + 1];
        int m2 = smc[SM_MSK + base + 2], m3 = smc[SM_MSK + base + 3];
        int c = m0 + m1 + m2 + m3;
        int sc = c;
        #pragma unroll
        for (int o = 1; o < 32; o <<= 1) {
            int t = __shfl_up_sync(0xFFFFFFFFu, sc, o);
            if (lane >= o) sc += t;
        }
        int run = sc - c;
        pos[base]     = (short)run; run += m0;
        pos[base + 1] = (short)run; run += m1;
        pos[base + 2] = (short)run; run += m2;
        pos[base + 3] = (short)run; run += m3;
        if (lane == 31) flg[1] = run;
    }
    __syncthreads();
    const int nc = flg[1];
    const int ntiles = (nc + 15) >> 4;
    const int scount = (ntiles + 1 - wp) >> 1;    // tiles for this warp (tt = 2s+wp)

    // ---- X load + fp16 convert + compacted store ----
    __half* Bh = (__half*)(smc + SM_BH);
    #pragma unroll 4
    for (int it = 0; it < 8; it++) {
        int e = tid + it * NTH;          // 0..8191 float4s
        int c = e >> 5;
        int q = (e & 31) * 4;
        float4 v = *(const float4*)(xb + (size_t)c * HW + q);
        float vv[4] = {v.x, v.y, v.z, v.w};
        #pragma unroll
        for (int i = 0; i < 4; i++) {
            if (smc[SM_MSK + q + i])
                Bh[c * BPITCH + pos[q + i]] = __float2half_rn(vv[i]);
        }
    }

    float acc[4][2][4];
    #pragma unroll
    for (int s = 0; s < 4; s++)
        #pragma unroll
        for (int jl = 0; jl < 2; jl++)
            #pragma unroll
            for (int r = 0; r < 4; r++) acc[s][jl][r] = 0.f;

    // warp-constant smem address bases
    const uint32_t a_base = (uint32_t)((wd * 16 + l15) * WPITCH + l16) * 2;
    const uint32_t b_base = sb + SM_BH + (uint32_t)(l15 * BPITCH + wp * 16 + l16) * 2;

    // ---- 8-chunk K loop (k=64 each): chunks 0-3 = GEMM1, 4-7 = GEMM2 ----
    #pragma unroll 1
    for (int kc = 0; kc < NCHUNK; kc++) {
        asm volatile("cp.async.wait_group 0;" ::: "memory");
        __syncthreads();   // chunk kc visible; all warps done with compute(kc-1)

        // prefetch kc+1 into the buffer freed by kc-1 (safe: post-barrier)
        if (kc + 1 < NCHUNK) {
            copy_chunk(sb, kc + 1, tid);
            asm volatile("cp.async.commit_group;" ::: "memory");
        }

        if (kc == 4) {
            // ---- H epilogue: bias + relu -> fp16 into Bh ----
            int r0 = wd * 16 + g;
            float bv0 = b1g[r0], bv1 = b1g[r0 + 8];
            #pragma unroll
            for (int s = 0; s < 4; s++) {
                if (s >= scount) break;
                int tt = 2 * s + wp;
                #pragma unroll
                for (int jl = 0; jl < 2; jl++) {
                    int px = tt * 16 + jl * 8 + tc * 2;
                    float h00 = fmaxf(acc[s][jl][0] + bv0, 0.f);
                    float h01 = fmaxf(acc[s][jl][1] + bv0, 0.f);
                    float h10 = fmaxf(acc[s][jl][2] + bv1, 0.f);
                    float h11 = fmaxf(acc[s][jl][3] + bv1, 0.f);
                    *(uint32_t*)&Bh[r0 * BPITCH + px] =
                        hpack(__float2half_rn(h00), __float2half_rn(h01));
                    *(uint32_t*)&Bh[(r0 + 8) * BPITCH + px] =
                        hpack(__float2half_rn(h10), __float2half_rn(h11));
                    #pragma unroll
                    for (int r = 0; r < 4; r++) acc[s][jl][r] = 0.f;
                }
            }
            __syncthreads();   // H visible before GEMM2 reads B
        }

        // ---- compute chunk kc: 4 k-steps of 16 ----
        const uint32_t wb = sb + SM_W + (kc & 1) * CHUNK_B + a_base;
        const uint32_t bb = b_base + (uint32_t)((kc & 3) * 64) * (BPITCH * 2);
        #pragma unroll 2
        for (int ks = 0; ks < 4; ks++) {
            uint32_t a[4];
            ldsm_x4(a, wb + ks * 32);
            const uint32_t bks = bb + (uint32_t)(ks * 16) * (BPITCH * 2);
            #pragma unroll
            for (int s = 0; s < 4; s++) {
                if (s >= scount) break;
                uint32_t bh[4];
                // column offset: tt*16 = 32s + 16wp halfs; wp*16 is in b_base -> stride s*32 halfs
                ldsm_x4_t(bh, bks + (uint32_t)(s * 32) * 2);
                mma_f16(acc[s][0], a, &bh[0]);
                mma_f16(acc[s][1], a, &bh[2]);
            }
        }
    }

    // ---- stage Y (bias added) into smem, aliasing Bh + W ring ----
    __syncthreads();   // all warps done reading Bh / W ring
    float* Ys = (float*)(smc + SM_BH);   // [256][YPITCH] fp32 (135168 B)
    {
        int r0 = wd * 16 + g;
        float bv0 = b2g[r0], bv1 = b2g[r0 + 8];
        #pragma unroll
        for (int s = 0; s < 4; s++) {
            if (s >= scount) break;
            int tt = 2 * s + wp;
            #pragma unroll
            for (int jl = 0; jl < 2; jl++) {
                int pc = tt * 16 + jl * 8 + tc * 2;
                if (pc < nc) {
                    Ys[r0 * YPITCH + pc]       = acc[s][jl][0] + bv0;
                    Ys[(r0 + 8) * YPITCH + pc] = acc[s][jl][2] + bv1;
                }
                if (pc + 1 < nc) {
                    Ys[r0 * YPITCH + pc + 1]       = acc[s][jl][1] + bv0;
                    Ys[(r0 + 8) * YPITCH + pc + 1] = acc[s][jl][3] + bv1;
                }
            }
        }
    }
    __syncthreads();

    // ---- blended coalesced output: out = mask ? Y : x ----
    float* ob = out + (size_t)b * 256 * HW + p0;
    #pragma unroll 4
    for (int it = 0; it < 16; it++) {
        int e2 = tid + it * NTH;         // float2 index, 16384 total
        int c = e2 >> 6;
        int q = (e2 & 63) * 2;
        float2 v = *(const float2*)(xb + (size_t)c * HW + q);
        float2 o = v;
        if (smc[SM_MSK + q])     o.x = Ys[c * YPITCH + pos[q]];
        if (smc[SM_MSK + q + 1]) o.y = Ys[c * YPITCH + pos[q + 1]];
        *(float2*)(ob + (size_t)c * HW + q) = o;
    }
}

extern "C" void kernel_launch(void* const* d_in, const int* in_sizes, int n_in,
                              void* d_out, int out_size)
{
    const float* x    = (const float*)d_in[0];
    const void*  mask = d_in[1];
    const float* W1   = (const float*)d_in[2];
    const float* b1   = (const float*)d_in[3];
    const float* W2   = (const float*)d_in[4];
    const float* b2   = (const float*)d_in[5];
    float*       out  = (float*)d_out;

    prep_weights_kernel<<<256, 256>>>(W1, W2);

    cudaFuncSetAttribute(mlp_mma_kernel,
                         cudaFuncAttributeMaxDynamicSharedMemorySize, SM_TOTAL);
    mlp_mma_kernel<<<2048, NTH, SM_TOTAL>>>(x, mask, b1, b2, out);
}

// round 14
// speedup vs baseline: 1.2538x; 1.1035x over previous
#include <cuda_runtime.h>
#include <cuda_fp16.h>
#include <cstdint>

#define HW 16384
#define NTH 512       // 16 warps per CTA; 2 CTAs/SM
#define PTILE 64      // pixels per CTA
#define BPITCH 72     // B smem pitch (halfs): 36 words = 4 mod 32 -> conflict-free ldsm
#define YPITCH 68     // Y smem pitch (floats)
#define WPITCH 72     // W smem pitch (halfs) per 64-k chunk
#define NCHUNK 8      // 8 chunks of k=64: W1[0..3] then W2[4..7]
#define CHUNK_B 36864
#define CHUNK_E 18432

// ---- smem layout (bytes), per CTA ----
#define SM_BH   0                 // 36864 (X/H fp16; Ys fp32 aliases BH+W0 after GEMM2)
#define SM_W    36864             // 2 x 36864 ping-pong -> ends 110592
#define SM_MSK  110592            // 64
#define SM_POS  110720            // 64 x int16
#define SM_FLG  110848            // ints
#define SM_TOTAL 110976           // x2 CTAs = 221952 <= 227KB

__device__ __align__(16) __half g_Ws[NCHUNK * CHUNK_E];

// ---------------- weight prep: transpose + fp16, k=64 chunked layout ----------------
extern "C" __global__ void prep_weights_kernel(const float* __restrict__ W1,
                                               const float* __restrict__ W2)
{
    int k = blockIdx.x;      // input channel (K dim of WT)
    int m = threadIdx.x;     // output channel
    int ch = k >> 6, kk = k & 63;
    g_Ws[ch * CHUNK_E + m * WPITCH + kk]       = __float2half_rn(W1[k * 256 + m]);
    g_Ws[(4 + ch) * CHUNK_E + m * WPITCH + kk] = __float2half_rn(W2[k * 256 + m]);
}

// ---------------- helpers ----------------
__device__ __forceinline__ void ldsm_x4(uint32_t* r, uint32_t addr) {
    asm volatile("ldmatrix.sync.aligned.m8n8.x4.shared.b16 {%0,%1,%2,%3}, [%4];"
                 : "=r"(r[0]), "=r"(r[1]), "=r"(r[2]), "=r"(r[3]) : "r"(addr));
}
__device__ __forceinline__ void ldsm_x4_t(uint32_t* r, uint32_t addr) {
    asm volatile("ldmatrix.sync.aligned.m8n8.x4.trans.shared.b16 {%0,%1,%2,%3}, [%4];"
                 : "=r"(r[0]), "=r"(r[1]), "=r"(r[2]), "=r"(r[3]) : "r"(addr));
}
__device__ __forceinline__ void mma_f16(float* d, const uint32_t* a, const uint32_t* b) {
    asm volatile("mma.sync.aligned.m16n8k16.row.col.f32.f16.f16.f32 "
                 "{%0,%1,%2,%3}, {%4,%5,%6,%7}, {%8,%9}, {%0,%1,%2,%3};"
                 : "+f"(d[0]), "+f"(d[1]), "+f"(d[2]), "+f"(d[3])
                 : "r"(a[0]), "r"(a[1]), "r"(a[2]), "r"(a[3]), "r"(b[0]), "r"(b[1]));
}
__device__ __forceinline__ void cp16(uint32_t dst, const void* src) {
    asm volatile("cp.async.cg.shared.global [%0], [%1], 16;" :: "r"(dst), "l"(src));
}
__device__ __forceinline__ uint32_t hpack(__half a, __half b) {
    __half2 t = __halves2half2(a, b);
    return *reinterpret_cast<uint32_t*>(&t);
}
__device__ __forceinline__ void copy_chunk(uint32_t sb, int ch, int tid) {
    uint32_t dst = sb + SM_W + (ch & 1) * CHUNK_B;
    const char* src = (const char*)(g_Ws + (size_t)ch * CHUNK_E);
    #pragma unroll
    for (int t = 0; t < 5; t++) {
        int line = tid + t * NTH;          // 2304 lines of 16B
        if (line < 2304) cp16(dst + line * 16, src + line * 16);
    }
}

// ---------------- main fused masked-MLP kernel ----------------
extern "C" __global__ void __launch_bounds__(NTH, 2)
mlp_mma_kernel(const float* __restrict__ x,
               const void* __restrict__ mask,
               const float* __restrict__ b1g,
               const float* __restrict__ b2g,
               float* __restrict__ out)
{
    extern __shared__ char smc[];
    const uint32_t sb = (uint32_t)__cvta_generic_to_shared(smc);
    int* flg = (int*)(smc + SM_FLG);
    short* pos = (short*)(smc + SM_POS);

    const int tid = threadIdx.x, lane = tid & 31, wid = tid >> 5;   // wid = wd 0..15
    const int g = lane >> 2, tc = lane & 3;
    const int l15 = lane & 15, l16 = (lane >> 4) * 8;
    const int b = blockIdx.x >> 8, p0 = (blockIdx.x & 255) * PTILE;
    const float* xb = x + (size_t)b * 256 * HW + p0;
    const int gi0 = b * HW + p0;

    // ---- kick off first weight chunk immediately ----
    copy_chunk(sb, 0, tid);
    asm volatile("cp.async.commit_group;" ::: "memory");

    // ---- per-CTA mask dtype detection (16 words cover 64 px in all encodings) ----
    if (tid < 16) {
        unsigned w = ((const unsigned*)mask)[gi0 / 4 + tid];
        bool fl = (w == 0x3F800000u);
        bool by = (w > 1u) && !fl;
        unsigned bb = __ballot_sync(0xFFFFu, by);
        if (tid == 0) flg[0] = bb ? 1 : 0;
    }
    __syncthreads();

    if (tid < PTILE) {
        int mv;
        if (flg[0]) mv = (((const unsigned char*)mask)[gi0 + tid] != 0);
        else        mv = (((const int*)mask)[gi0 + tid] != 0);
        smc[SM_MSK + tid] = (char)mv;
    }
    __syncthreads();

    // ---- warp 0: prefix scan over 64 px -> per-pixel pos[] / nc ----
    if (wid == 0) {
        int base = lane * 2;
        int m0 = smc[SM_MSK + base], m1 = smc[SM_MSK + base + 1];
        int c = m0 + m1;
        int sc = c;
        #pragma unroll
        for (int o = 1; o < 32; o <<= 1) {
            int t = __shfl_up_sync(0xFFFFFFFFu, sc, o);
            if (lane >= o) sc += t;
        }
        int run = sc - c;
        pos[base]     = (short)run; run += m0;
        pos[base + 1] = (short)run; run += m1;
        if (lane == 31) flg[1] = run;
    }
    __syncthreads();
    const int nc = flg[1];
    const int ntiles = (nc + 15) >> 4;   // 0..4

    // ---- X load + fp16 convert + compacted store ----
    __half* Bh = (__half*)(smc + SM_BH);
    #pragma unroll 4
    for (int it = 0; it < 8; it++) {
        int e = tid + it * NTH;          // 0..4095 float4s
        int c = e >> 4;                  // 16 float4 per 64-px row
        int q = (e & 15) * 4;
        float4 v = *(const float4*)(xb + (size_t)c * HW + q);
        float vv[4] = {v.x, v.y, v.z, v.w};
        #pragma unroll
        for (int i = 0; i < 4; i++) {
            if (smc[SM_MSK + q + i])
                Bh[c * BPITCH + pos[q + i]] = __float2half_rn(vv[i]);
        }
    }

    float acc[4][2][4];
    #pragma unroll
    for (int s = 0; s < 4; s++)
        #pragma unroll
        for (int jl = 0; jl < 2; jl++)
            #pragma unroll
            for (int r = 0; r < 4; r++) acc[s][jl][r] = 0.f;

    // warp-constant smem address bases
    const uint32_t a_base = (uint32_t)((wid * 16 + l15) * WPITCH + l16) * 2;
    const uint32_t b_base = sb + SM_BH + (uint32_t)(l15 * BPITCH + l16) * 2;

    // ---- 8-chunk K loop (k=64 each): chunks 0-3 = GEMM1, 4-7 = GEMM2 ----
    #pragma unroll 1
    for (int kc = 0; kc < NCHUNK; kc++) {
        asm volatile("cp.async.wait_group 0;" ::: "memory");
        __syncthreads();   // chunk kc visible; all warps done with compute(kc-1)

        if (kc + 1 < NCHUNK) {
            copy_chunk(sb, kc + 1, tid);
            asm volatile("cp.async.commit_group;" ::: "memory");
        }

        if (kc == 4) {
            // ---- H epilogue: bias + relu -> fp16 into Bh ----
            int r0 = wid * 16 + g;
            float bv0 = b1g[r0], bv1 = b1g[r0 + 8];
            #pragma unroll
            for (int s = 0; s < 4; s++) {
                if (s >= ntiles) break;
                #pragma unroll
                for (int jl = 0; jl < 2; jl++) {
                    int px = s * 16 + jl * 8 + tc * 2;
                    float h00 = fmaxf(acc[s][jl][0] + bv0, 0.f);
                    float h01 = fmaxf(acc[s][jl][1] + bv0, 0.f);
                    float h10 = fmaxf(acc[s][jl][2] + bv1, 0.f);
                    float h11 = fmaxf(acc[s][jl][3] + bv1, 0.f);
                    *(uint32_t*)&Bh[r0 * BPITCH + px] =
                        hpack(__float2half_rn(h00), __float2half_rn(h01));
                    *(uint32_t*)&Bh[(r0 + 8) * BPITCH + px] =
                        hpack(__float2half_rn(h10), __float2half_rn(h11));
                    #pragma unroll
                    for (int r = 0; r < 4; r++) acc[s][jl][r] = 0.f;
                }
            }
            __syncthreads();   // H visible before GEMM2 reads B
        }

        // ---- compute chunk kc: 4 k-steps of 16 ----
        const uint32_t wb = sb + SM_W + (kc & 1) * CHUNK_B + a_base;
        const uint32_t bb = b_base + (uint32_t)((kc & 3) * 64) * (BPITCH * 2);
        #pragma unroll 2
        for (int ks = 0; ks < 4; ks++) {
            uint32_t a[4];
            ldsm_x4(a, wb + ks * 32);
            const uint32_t bks = bb + (uint32_t)(ks * 16) * (BPITCH * 2);
            #pragma unroll
            for (int s = 0; s < 4; s++) {
                if (s >= ntiles) break;
                uint32_t bh[4];
                ldsm_x4_t(bh, bks + (uint32_t)(s * 16) * 2);   // col s*16 halfs
                mma_f16(acc[s][0], a, &bh[0]);
                mma_f16(acc[s][1], a, &bh[2]);
            }
        }
    }

    // ---- stage Y (bias added) into smem, aliasing Bh + W0 ----
    __syncthreads();   // all warps done reading Bh / W ring
    float* Ys = (float*)(smc + SM_BH);   // [256][YPITCH] fp32 = 69632 B
    {
        int r0 = wid * 16 + g;
        float bv0 = b2g[r0], bv1 = b2g[r0 + 8];
        #pragma unroll
        for (int s = 0; s < 4; s++) {
            if (s >= ntiles) break;
            #pragma unroll
            for (int jl = 0; jl < 2; jl++) {
                int pc = s * 16 + jl * 8 + tc * 2;
                if (pc < nc) {
                    Ys[r0 * YPITCH + pc]       = acc[s][jl][0] + bv0;
                    Ys[(r0 + 8) * YPITCH + pc] = acc[s][jl][2] + bv1;
                }
                if (pc + 1 < nc) {
                    Ys[r0 * YPITCH + pc + 1]       = acc[s][jl][1] + bv0;
                    Ys[(r0 + 8) * YPITCH + pc + 1] = acc[s][jl][3] + bv1;
                }
            }
        }
    }
    __syncthreads();

    // ---- blended coalesced output: out = mask ? Y : x ----
    float* ob = out + (size_t)b * 256 * HW + p0;
    #pragma unroll 4
    for (int it = 0; it < 16; it++) {
        int e2 = tid + it * NTH;         // float2 index, 8192 total
        int c = e2 >> 5;                 // 32 float2 per 64-px row
        int q = (e2 & 31) * 2;
        float2 v = *(const float2*)(xb + (size_t)c * HW + q);
        float2 o = v;
        if (smc[SM_MSK + q])     o.x = Ys[c * YPITCH + pos[q]];
        if (smc[SM_MSK + q + 1]) o.y = Ys[c * YPITCH + pos[q + 1]];
        *(float2*)(ob + (size_t)c * HW + q) = o;
    }
}

extern "C" void kernel_launch(void* const* d_in, const int* in_sizes, int n_in,
                              void* d_out, int out_size)
{
    const float* x    = (const float*)d_in[0];
    const void*  mask = d_in[1];
    const float* W1   = (const float*)d_in[2];
    const float* b1   = (const float*)d_in[3];
    const float* W2   = (const float*)d_in[4];
    const float* b2   = (const float*)d_in[5];
    float*       out  = (float*)d_out;

    prep_weights_kernel<<<256, 256>>>(W1, W2);

    cudaFuncSetAttribute(mlp_mma_kernel,
                         cudaFuncAttributeMaxDynamicSharedMemorySize, SM_TOTAL);
    // 16 batches * 256 pixel tiles = 4096 CTAs, 2 CTAs/SM
    mlp_mma_kernel<<<4096, NTH, SM_TOTAL>>>(x, mask, b1, b2, out);
}